// round 16
// baseline (speedup 1.0000x reference)
#include <cuda_runtime.h>
#include <cuda_bf16.h>
#include <cstdint>

#define N_PATHS 2048
#define N_STEPS 512
#define N_FWD   40
#define DT      (1.0f / 512.0f)
#define SHIFT   0.02f
#define LOG2E   1.4426950408889634f

#define KC      32                    // conv k-chunk
#define SA      36                    // padded row stride (floats)
#define TILE_U  (128 * SA)            // uint32s per B tile
#define E_ROWS  608                   // extended band rows (max, ti=3)

#define PPB     4                     // paths per block in k_path
#define HALF    (N_STEPS / 2)         // 256
#define PT2     (2 * PPB * N_FWD)     // 320 threads (2 t-halves)

// ---------------- device scratch ----------------
__device__ float  g_cw2[N_STEPS];               // inclusive prefix sum of w^2
__device__ float4 g_fbm4[N_PATHS * N_STEPS];    // fbm4[p][t][0..3]

// Toeplitz weight, cancellation-free in fp32:
// w[j] = ((j+1)^0.6 - j^0.6)/0.6 * 2^3.6 / Gamma(0.6)
__device__ __forceinline__ float toeplitz_w(int j) {
    const float scale = 12.125732f / 1.4891922f;
    float num;
    if (j == 0) {
        num = 1.0f / 0.6f;
    } else {
        float fj = (float)j;
        float p6 = exp2f(0.6f * log2f(fj));
        float em = expm1f(0.6f * log1pf(1.0f / fj));
        num = p6 * em * (1.0f / 0.6f);
    }
    return num * scale;
}

__device__ __forceinline__ uint32_t f2tf32(float f) {
    uint32_t u;
    asm("cvt.rna.tf32.f32 %0, %1;" : "=r"(u) : "f"(f));
    return u;
}

__device__ __forceinline__ void mma_tf32(float* c, const uint32_t* a, const uint32_t* b) {
    asm volatile(
        "mma.sync.aligned.m16n8k8.row.col.f32.tf32.tf32.f32 "
        "{%0,%1,%2,%3}, {%4,%5,%6,%7}, {%8,%9}, {%0,%1,%2,%3};"
        : "+f"(c[0]), "+f"(c[1]), "+f"(c[2]), "+f"(c[3])
        : "r"(a[0]), "r"(a[1]), "r"(a[2]), "r"(a[3]), "r"(b[0]), "r"(b[1]));
}

// ---------------- kernel 1: triangular Toeplitz GEMM (tf32 HMMA) ------------
// Extended-band A staged once (window per chunk = pointer offset);
// B double-buffered via register prefetch. RNA tf32 rounding (accuracy).
__global__ __launch_bounds__(256) void k_conv_mma(const float* __restrict__ dz) {
    extern __shared__ uint32_t dsm[];
    uint32_t* sE    = dsm;                              // E_ROWS * SA
    uint32_t* sB    = dsm + E_ROWS * SA;                // 2 * TILE_U
    float*    swf   = (float*)(sB + 2 * TILE_U);        // 512
    float*    sscan = swf + N_STEPS;                    // 256

    const int tid  = threadIdx.x;
    const int wid  = tid >> 5;
    const int lane = tid & 31;
    const int bid  = blockIdx.x;
    const int ti   = 3 - (bid >> 6);     // heavy tiles first
    const int cg   = bid & 63;
    const int p0   = cg * 32;
    const int t0   = 128 * ti;
    const int mw   = (wid >> 2) * 64;
    const int nw   = (wid & 3) * 32;

    const int n_kc = 4 * ti + 4;
    const int BIAS = 32 * (n_kc - 1);    // = 128*ti + 96
    const int rows = 128 + BIAS;

    for (int i = tid; i < N_STEPS; i += 256) swf[i] = toeplitz_w(i);
    __syncthreads();

    if (bid == 0) {
        float wa = swf[2 * tid], wb = swf[2 * tid + 1];
        float w2b = wb * wb;
        sscan[tid] = wa * wa + w2b;
        __syncthreads();
        #pragma unroll
        for (int off = 1; off < 256; off <<= 1) {
            float v = sscan[tid];
            float u = (tid >= off) ? sscan[tid - off] : 0.f;
            __syncthreads();
            sscan[tid] = v + u;
            __syncthreads();
        }
        float inc = sscan[tid];
        g_cw2[2 * tid + 1] = inc;
        g_cw2[2 * tid]     = inc - w2b;
        __syncthreads();
    }

    // ---- stage extended band E once: E[r][j] = w[r - 96 - j] ----
    for (int idx = tid; idx < rows * KC; idx += 256) {
        int r = idx >> 5, j = idx & 31;
        int q = r - 96 - j;
        float v = (q >= 0) ? swf[q] : 0.f;
        sE[r * SA + j] = f2tf32(v);
    }

    const float4* dzv = (const float4*)dz;

    // ---- stage B chunk 0 ----
    #pragma unroll
    for (int r = 0; r < 4; ++r) {
        int u2 = tid + 256 * r;
        int pl = u2 >> 5, k = u2 & 31;
        float4 x = dzv[(size_t)(p0 + pl) * N_STEPS + k];
        int nn = 4 * pl;
        sB[(nn + 0) * SA + k] = f2tf32(x.x);
        sB[(nn + 1) * SA + k] = f2tf32(x.y);
        sB[(nn + 2) * SA + k] = f2tf32(x.z);
        sB[(nn + 3) * SA + k] = f2tf32(x.w);
    }
    __syncthreads();

    float c[4][4][4];
    #pragma unroll
    for (int mt = 0; mt < 4; ++mt)
        #pragma unroll
        for (int nt = 0; nt < 4; ++nt)
            #pragma unroll
            for (int e = 0; e < 4; ++e) c[mt][nt][e] = 0.f;

    for (int kc = 0; kc < n_kc; ++kc) {
        const uint32_t* Acur = sE + (BIAS - 32 * kc) * SA;   // window into E
        const uint32_t* Bcur = sB + (kc & 1) * TILE_U;
        uint32_t*       Bnxt = sB + ((kc + 1) & 1) * TILE_U;
        const bool pref = (kc + 1 < n_kc);

        float4 xr[4];
        if (pref) {
            int s0n = KC * (kc + 1);
            #pragma unroll
            for (int r = 0; r < 4; ++r) {
                int u2 = tid + 256 * r;
                int pl = u2 >> 5, k = u2 & 31;
                xr[r] = dzv[(size_t)(p0 + pl) * N_STEPS + s0n + k];
            }
        }

        #pragma unroll
        for (int ks = 0; ks < 4; ++ks) {
            int kb = 8 * ks;
            uint32_t bf[4][2];
            #pragma unroll
            for (int nt = 0; nt < 4; ++nt) {
                int col = nw + 8 * nt + (lane >> 2);
                bf[nt][0] = Bcur[col * SA + kb + (lane & 3)];
                bf[nt][1] = Bcur[col * SA + kb + 4 + (lane & 3)];
            }
            #pragma unroll
            for (int mt = 0; mt < 4; ++mt) {
                int row = mw + 16 * mt + (lane >> 2);
                uint32_t af[4];
                af[0] = Acur[row * SA + kb + (lane & 3)];
                af[1] = Acur[(row + 8) * SA + kb + (lane & 3)];
                af[2] = Acur[row * SA + kb + 4 + (lane & 3)];
                af[3] = Acur[(row + 8) * SA + kb + 4 + (lane & 3)];
                #pragma unroll
                for (int nt = 0; nt < 4; ++nt)
                    mma_tf32(c[mt][nt], af, bf[nt]);
            }
        }

        if (pref) {
            #pragma unroll
            for (int r = 0; r < 4; ++r) {
                int u2 = tid + 256 * r;
                int pl = u2 >> 5, k = u2 & 31;
                int nn = 4 * pl;
                Bnxt[(nn + 0) * SA + k] = f2tf32(xr[r].x);
                Bnxt[(nn + 1) * SA + k] = f2tf32(xr[r].y);
                Bnxt[(nn + 2) * SA + k] = f2tf32(xr[r].z);
                Bnxt[(nn + 3) * SA + k] = f2tf32(xr[r].w);
            }
        }
        __syncthreads();
    }

    float2* dst = (float2*)g_fbm4;
    #pragma unroll
    for (int mt = 0; mt < 4; ++mt) {
        #pragma unroll
        for (int nt = 0; nt < 4; ++nt) {
            int row  = mw + 16 * mt + (lane >> 2);
            int col  = nw + 8 * nt + 2 * (lane & 3);
            int path = p0 + (col >> 2);
            int dp   = (col & 3) >> 1;
            size_t base = ((size_t)path * N_STEPS + t0 + row) * 2 + dp;
            dst[base]      = make_float2(c[mt][nt][0], c[mt][nt][1]);
            dst[base + 16] = make_float2(c[mt][nt][2], c[mt][nt][3]);
        }
    }
}

// ---------------- kernel 2: half-split single-pass scan ---------------------
// 320 threads = (half h 0..1) x (pl 0..3) x (n 0..39). Thread h0 scans
// t=[0,256) with stores; h1 recomputes the identical accumulation over
// [0,256) (no stores -> bit-identical acc at t=256) then scans [256,512)
// with stores. 2x warps at the same smem -> ~47% occupancy.
__global__ __launch_bounds__(PT2, 3) void k_path(
    const float* __restrict__ dz,
    const float* __restrict__ F0,
    const float* __restrict__ alphas,
    const float* __restrict__ rhos,
    const float* __restrict__ nus,
    const float* __restrict__ tau,
    const float* __restrict__ L,
    const float* __restrict__ Lam,
    float* __restrict__ out)
{
    extern __shared__ float4 smem[];               // [2][PPB][N_STEPS] = 64 KB
    float4* sfb = smem;
    float4* sdz = smem + PPB * N_STEPS;
    __shared__ float som[N_FWD];

    const int u  = threadIdx.x;                    // 0..319
    const int h  = u / (PPB * N_FWD);              // t-half 0/1
    const int r0 = u - h * (PPB * N_FWD);          // 0..159
    const int pl = r0 / N_FWD;                     // 0..3
    const int n  = r0 - pl * N_FWD;                // 0..39
    const int p0 = blockIdx.x * PPB;

    // ---- stage: coalesced (2048 float4 per array / 320 threads) ----
    const float4* fbg = &g_fbm4[(size_t)p0 * N_STEPS];
    const float4* dzg = (const float4*)dz + (size_t)p0 * N_STEPS;
    for (int i = u; i < PPB * N_STEPS; i += PT2) {
        sfb[i] = fbg[i];
        float4 d = dzg[i];
        d.w = g_cw2[i & (N_STEPS - 1)];
        sdz[i] = d;
    }
    if (u < N_FWD) {
        float f0m = F0[u];
        float vsm = alphas[u] * sqrtf(fabsf(f0m + SHIFT));
        som[u] = tau[u] * vsm / (1.f + tau[u] * f0m);
    }

    // ---- per-n constants ----
    float f0n = F0[n];
    float vs  = alphas[n] * sqrtf(fabsf(f0n + SHIFT));
    float rho = rhos[n];
    float nu  = nus[n];
    float sq  = sqrtf(fmaxf(1.f - rho * rho, 0.f));
    float l0 = L[n * 3 + 0], l1 = L[n * 3 + 1], l2 = L[n * 3 + 2];
    float a0 = nu * rho * l0 * LOG2E;
    float a1 = nu * rho * l1 * LOG2E;
    float a2 = nu * rho * l2 * LOG2E;
    float a3 = nu * sq * LOG2E;
    float bb = 0.5f * nu * nu * DT * LOG2E;
    float w0 = vs * l0, w1 = vs * l1, w2 = vs * l2;

    __syncthreads();

    float mdot = 0.f;
    #pragma unroll 8
    for (int m = 0; m < N_FWD; ++m)
        mdot = fmaf(Lam[n * N_FWD + m], som[m], mdot);
    float mu0dt = -vs * mdot * DT;

    const float4* fbp = sfb + pl * N_STEPS;
    const float4* dzp = sdz + pl * N_STEPS;
    float acc = f0n;
    float* op = out + (size_t)(p0 + pl) * 513 * N_FWD + n;

#define DF_VAL(t, dest)                                           \
    do {                                                          \
        float4 fv = fbp[t];                                       \
        float4 dv = dzp[t];                                       \
        float arg = fmaf(a0, fv.x,                                \
                    fmaf(a1, fv.y,                                \
                    fmaf(a2, fv.z,                                \
                    fmaf(a3, fv.w, -bb * dv.w))));                \
        float uv;                                                 \
        asm("ex2.approx.f32 %0, %1;" : "=f"(uv) : "f"(arg));      \
        float wr = fmaf(w0, dv.x, fmaf(w1, dv.y, w2 * dv.z));     \
        dest = fmaf(uv, fmaf(mu0dt, uv, wr), dest);               \
    } while (0)

    if (h == 0) {
        __stcs(op, acc);                           // row 0 = F0
        op += N_FWD;
        #pragma unroll 4
        for (int t = 0; t < HALF; ++t) {
            DF_VAL(t, acc);
            __stcs(op, acc);
            op += N_FWD;
        }
    } else {
        // recompute first half (identical chain -> bit-identical acc)
        #pragma unroll 4
        for (int t = 0; t < HALF; ++t)
            DF_VAL(t, acc);
        op += (size_t)(HALF + 1) * N_FWD;          // first store = row HALF+1
        #pragma unroll 4
        for (int t = HALF; t < N_STEPS; ++t) {
            DF_VAL(t, acc);
            __stcs(op, acc);
            op += N_FWD;
        }
    }
#undef DF_VAL
}

extern "C" void kernel_launch(void* const* d_in, const int* in_sizes, int n_in,
                              void* d_out, int out_size) {
    const float* dz     = (const float*)d_in[0];
    const float* F0     = (const float*)d_in[1];
    const float* alphas = (const float*)d_in[2];
    const float* rhos   = (const float*)d_in[3];
    const float* nus    = (const float*)d_in[4];
    const float* tau    = (const float*)d_in[5];
    const float* L      = (const float*)d_in[6];
    const float* Lam    = (const float*)d_in[7];
    float* out = (float*)d_out;

    const int smem_conv = (E_ROWS * SA + 2 * TILE_U + N_STEPS + 256) * 4;  // ~124.5 KB
    const int smem_path = 2 * PPB * N_STEPS * (int)sizeof(float4);         // 64 KB
    cudaFuncSetAttribute(k_conv_mma, cudaFuncAttributeMaxDynamicSharedMemorySize, smem_conv);
    cudaFuncSetAttribute(k_path, cudaFuncAttributeMaxDynamicSharedMemorySize, smem_path);

    k_conv_mma<<<256, 256, smem_conv>>>(dz);
    k_path<<<N_PATHS / PPB, PT2, smem_path>>>(dz, F0, alphas, rhos, nus, tau, L, Lam, out);
}

// round 17
// speedup vs baseline: 1.7844x; 1.7844x over previous
#include <cuda_runtime.h>
#include <cuda_bf16.h>
#include <cstdint>

#define N_PATHS 2048
#define N_STEPS 512
#define N_FWD   40
#define DT      (1.0f / 512.0f)
#define SHIFT   0.02f
#define LOG2E   1.4426950408889634f

#define KC      32                    // conv k-chunk
#define SA      36                    // padded row stride (floats)
#define TILE_U  (128 * SA)            // uint32s per B tile
#define E_ROWS  608                   // extended band rows (max, ti=3)

#define PPB     4                     // paths per block in k_path
#define PT      (PPB * N_FWD)         // 160 threads

// ---------------- device scratch ----------------
__device__ float  g_cw2[N_STEPS];               // inclusive prefix sum of w^2
__device__ float4 g_fbm4[N_PATHS * N_STEPS];    // fbm4[p][t][0..3]

// Toeplitz weight, cancellation-free in fp32:
// w[j] = ((j+1)^0.6 - j^0.6)/0.6 * 2^3.6 / Gamma(0.6)
__device__ __forceinline__ float toeplitz_w(int j) {
    const float scale = 12.125732f / 1.4891922f;
    float num;
    if (j == 0) {
        num = 1.0f / 0.6f;
    } else {
        float fj = (float)j;
        float p6 = exp2f(0.6f * log2f(fj));
        float em = expm1f(0.6f * log1pf(1.0f / fj));
        num = p6 * em * (1.0f / 0.6f);
    }
    return num * scale;
}

// tf32 round-to-nearest via bit trick: HMMA.TF32 ignores the low 13 mantissa
// bits, so adding 0x1000 before HW truncation implements RN(A) at IADD cost.
__device__ __forceinline__ uint32_t f2tf32r(float f) {
    return __float_as_uint(f) + 0x1000u;
}

__device__ __forceinline__ void mma_tf32(float* c, const uint32_t* a, const uint32_t* b) {
    asm volatile(
        "mma.sync.aligned.m16n8k8.row.col.f32.tf32.tf32.f32 "
        "{%0,%1,%2,%3}, {%4,%5,%6,%7}, {%8,%9}, {%0,%1,%2,%3};"
        : "+f"(c[0]), "+f"(c[1]), "+f"(c[2]), "+f"(c[3])
        : "r"(a[0]), "r"(a[1]), "r"(a[2]), "r"(a[3]), "r"(b[0]), "r"(b[1]));
}

// ---------------- kernel 1: triangular Toeplitz GEMM (tf32 HMMA) ------------
// Extended-band A staged once (window per chunk = pointer offset);
// B double-buffered via register prefetch; bit-trick RN rounding.
__global__ __launch_bounds__(256) void k_conv_mma(const float* __restrict__ dz) {
    extern __shared__ uint32_t dsm[];
    uint32_t* sE    = dsm;                              // E_ROWS * SA
    uint32_t* sB    = dsm + E_ROWS * SA;                // 2 * TILE_U
    float*    swf   = (float*)(sB + 2 * TILE_U);        // 512
    float*    sscan = swf + N_STEPS;                    // 256

    const int tid  = threadIdx.x;
    const int wid  = tid >> 5;
    const int lane = tid & 31;
    const int bid  = blockIdx.x;
    const int ti   = 3 - (bid >> 6);     // heavy tiles first
    const int cg   = bid & 63;
    const int p0   = cg * 32;
    const int t0   = 128 * ti;
    const int mw   = (wid >> 2) * 64;
    const int nw   = (wid & 3) * 32;

    const int n_kc = 4 * ti + 4;
    const int BIAS = 32 * (n_kc - 1);    // = 128*ti + 96
    const int rows = 128 + BIAS;

    for (int i = tid; i < N_STEPS; i += 256) swf[i] = toeplitz_w(i);
    __syncthreads();

    if (bid == 0) {
        float wa = swf[2 * tid], wb = swf[2 * tid + 1];
        float w2b = wb * wb;
        sscan[tid] = wa * wa + w2b;
        __syncthreads();
        #pragma unroll
        for (int off = 1; off < 256; off <<= 1) {
            float v = sscan[tid];
            float u = (tid >= off) ? sscan[tid - off] : 0.f;
            __syncthreads();
            sscan[tid] = v + u;
            __syncthreads();
        }
        float inc = sscan[tid];
        g_cw2[2 * tid + 1] = inc;
        g_cw2[2 * tid]     = inc - w2b;
        __syncthreads();
    }

    // ---- stage extended band E once: E[r][j] = w[r - 96 - j] ----
    for (int idx = tid; idx < rows * KC; idx += 256) {
        int r = idx >> 5, j = idx & 31;
        int q = r - 96 - j;
        uint32_t v = (q >= 0) ? f2tf32r(swf[q]) : 0u;
        sE[r * SA + j] = v;
    }

    const float4* dzv = (const float4*)dz;

    // ---- stage B chunk 0 ----
    #pragma unroll
    for (int r = 0; r < 4; ++r) {
        int u2 = tid + 256 * r;
        int pl = u2 >> 5, k = u2 & 31;
        float4 x = dzv[(size_t)(p0 + pl) * N_STEPS + k];
        int nn = 4 * pl;
        sB[(nn + 0) * SA + k] = f2tf32r(x.x);
        sB[(nn + 1) * SA + k] = f2tf32r(x.y);
        sB[(nn + 2) * SA + k] = f2tf32r(x.z);
        sB[(nn + 3) * SA + k] = f2tf32r(x.w);
    }
    __syncthreads();

    float c[4][4][4];
    #pragma unroll
    for (int mt = 0; mt < 4; ++mt)
        #pragma unroll
        for (int nt = 0; nt < 4; ++nt)
            #pragma unroll
            for (int e = 0; e < 4; ++e) c[mt][nt][e] = 0.f;

    for (int kc = 0; kc < n_kc; ++kc) {
        const uint32_t* Acur = sE + (BIAS - 32 * kc) * SA;   // window into E
        const uint32_t* Bcur = sB + (kc & 1) * TILE_U;
        uint32_t*       Bnxt = sB + ((kc + 1) & 1) * TILE_U;
        const bool pref = (kc + 1 < n_kc);

        float4 xr[4];
        if (pref) {
            int s0n = KC * (kc + 1);
            #pragma unroll
            for (int r = 0; r < 4; ++r) {
                int u2 = tid + 256 * r;
                int pl = u2 >> 5, k = u2 & 31;
                xr[r] = dzv[(size_t)(p0 + pl) * N_STEPS + s0n + k];
            }
        }

        #pragma unroll
        for (int ks = 0; ks < 4; ++ks) {
            int kb = 8 * ks;
            uint32_t bf[4][2];
            #pragma unroll
            for (int nt = 0; nt < 4; ++nt) {
                int col = nw + 8 * nt + (lane >> 2);
                bf[nt][0] = Bcur[col * SA + kb + (lane & 3)];
                bf[nt][1] = Bcur[col * SA + kb + 4 + (lane & 3)];
            }
            #pragma unroll
            for (int mt = 0; mt < 4; ++mt) {
                int row = mw + 16 * mt + (lane >> 2);
                uint32_t af[4];
                af[0] = Acur[row * SA + kb + (lane & 3)];
                af[1] = Acur[(row + 8) * SA + kb + (lane & 3)];
                af[2] = Acur[row * SA + kb + 4 + (lane & 3)];
                af[3] = Acur[(row + 8) * SA + kb + 4 + (lane & 3)];
                #pragma unroll
                for (int nt = 0; nt < 4; ++nt)
                    mma_tf32(c[mt][nt], af, bf[nt]);
            }
        }

        if (pref) {
            #pragma unroll
            for (int r = 0; r < 4; ++r) {
                int u2 = tid + 256 * r;
                int pl = u2 >> 5, k = u2 & 31;
                int nn = 4 * pl;
                Bnxt[(nn + 0) * SA + k] = f2tf32r(xr[r].x);
                Bnxt[(nn + 1) * SA + k] = f2tf32r(xr[r].y);
                Bnxt[(nn + 2) * SA + k] = f2tf32r(xr[r].z);
                Bnxt[(nn + 3) * SA + k] = f2tf32r(xr[r].w);
            }
        }
        __syncthreads();
    }

    float2* dst = (float2*)g_fbm4;
    #pragma unroll
    for (int mt = 0; mt < 4; ++mt) {
        #pragma unroll
        for (int nt = 0; nt < 4; ++nt) {
            int row  = mw + 16 * mt + (lane >> 2);
            int col  = nw + 8 * nt + 2 * (lane & 3);
            int path = p0 + (col >> 2);
            int dp   = (col & 3) >> 1;
            size_t base = ((size_t)path * N_STEPS + t0 + row) * 2 + dp;
            dst[base]      = make_float2(c[mt][nt][0], c[mt][nt][1]);
            dst[base + 16] = make_float2(c[mt][nt][2], c[mt][nt][3]);
        }
    }
}

// ---------------- kernel 2: single-pass scan, two-bank pipeline (R13) -------
__global__ __launch_bounds__(PT, 3) void k_path(
    const float* __restrict__ dz,
    const float* __restrict__ F0,
    const float* __restrict__ alphas,
    const float* __restrict__ rhos,
    const float* __restrict__ nus,
    const float* __restrict__ tau,
    const float* __restrict__ L,
    const float* __restrict__ Lam,
    float* __restrict__ out)
{
    extern __shared__ float4 smem[];               // [2][PPB][N_STEPS] = 64 KB
    float4* sfb = smem;
    float4* sdz = smem + PPB * N_STEPS;
    __shared__ float som[N_FWD];

    const int u  = threadIdx.x;                    // 0..159
    const int pl = u / N_FWD;                      // 0..3
    const int n  = u - pl * N_FWD;                 // 0..39
    const int p0 = blockIdx.x * PPB;

    const float4* fbg = &g_fbm4[(size_t)p0 * N_STEPS];
    const float4* dzg = (const float4*)dz + (size_t)p0 * N_STEPS;
    for (int i = u; i < PPB * N_STEPS; i += PT) {
        sfb[i] = fbg[i];
        float4 d = dzg[i];
        d.w = g_cw2[i & (N_STEPS - 1)];
        sdz[i] = d;
    }
    if (u < N_FWD) {
        float f0m = F0[u];
        float vsm = alphas[u] * sqrtf(fabsf(f0m + SHIFT));
        som[u] = tau[u] * vsm / (1.f + tau[u] * f0m);
    }

    float f0n = F0[n];
    float vs  = alphas[n] * sqrtf(fabsf(f0n + SHIFT));
    float rho = rhos[n];
    float nu  = nus[n];
    float sq  = sqrtf(fmaxf(1.f - rho * rho, 0.f));
    float l0 = L[n * 3 + 0], l1 = L[n * 3 + 1], l2 = L[n * 3 + 2];
    float a0 = nu * rho * l0 * LOG2E;
    float a1 = nu * rho * l1 * LOG2E;
    float a2 = nu * rho * l2 * LOG2E;
    float a3 = nu * sq * LOG2E;
    float bb = 0.5f * nu * nu * DT * LOG2E;
    float w0 = vs * l0, w1 = vs * l1, w2 = vs * l2;

    __syncthreads();

    float mdot = 0.f;
    #pragma unroll 8
    for (int m = 0; m < N_FWD; ++m)
        mdot = fmaf(Lam[n * N_FWD + m], som[m], mdot);
    float mu0dt = -vs * mdot * DT;

    const float4* fbp = sfb + pl * N_STEPS;
    const float4* dzp = sdz + pl * N_STEPS;
    float acc = f0n;
    float* op = out + (size_t)(p0 + pl) * 513 * N_FWD + n;
    __stcs(op, acc);                               // row 0 = F0
    op += N_FWD;

#define SCAN_STEP(fv, dv)                                         \
    do {                                                          \
        float arg = fmaf(a0, (fv).x,                              \
                    fmaf(a1, (fv).y,                              \
                    fmaf(a2, (fv).z,                              \
                    fmaf(a3, (fv).w, -bb * (dv).w))));            \
        float uv;                                                 \
        asm("ex2.approx.f32 %0, %1;" : "=f"(uv) : "f"(arg));      \
        float wr = fmaf(w0, (dv).x, fmaf(w1, (dv).y, w2 * (dv).z)); \
        acc = fmaf(uv, fmaf(mu0dt, uv, wr), acc);                 \
        __stcs(op, acc);                                          \
        op += N_FWD;                                              \
    } while (0)

    float4 fA[4], dA[4], fB[4], dB[4];
    #pragma unroll
    for (int i = 0; i < 4; ++i) { fA[i] = fbp[i]; dA[i] = dzp[i]; }

    #pragma unroll 1
    for (int tb = 0; tb < N_STEPS; tb += 8) {
        #pragma unroll
        for (int i = 0; i < 4; ++i) { fB[i] = fbp[tb + 4 + i]; dB[i] = dzp[tb + 4 + i]; }
        #pragma unroll
        for (int i = 0; i < 4; ++i) SCAN_STEP(fA[i], dA[i]);
        if (tb + 8 < N_STEPS) {
            #pragma unroll
            for (int i = 0; i < 4; ++i) { fA[i] = fbp[tb + 8 + i]; dA[i] = dzp[tb + 8 + i]; }
        }
        #pragma unroll
        for (int i = 0; i < 4; ++i) SCAN_STEP(fB[i], dB[i]);
    }
#undef SCAN_STEP
}

extern "C" void kernel_launch(void* const* d_in, const int* in_sizes, int n_in,
                              void* d_out, int out_size) {
    const float* dz     = (const float*)d_in[0];
    const float* F0     = (const float*)d_in[1];
    const float* alphas = (const float*)d_in[2];
    const float* rhos   = (const float*)d_in[3];
    const float* nus    = (const float*)d_in[4];
    const float* tau    = (const float*)d_in[5];
    const float* L      = (const float*)d_in[6];
    const float* Lam    = (const float*)d_in[7];
    float* out = (float*)d_out;

    const int smem_conv = (E_ROWS * SA + 2 * TILE_U + N_STEPS + 256) * 4;  // ~124.5 KB
    const int smem_path = 2 * PPB * N_STEPS * (int)sizeof(float4);         // 64 KB
    cudaFuncSetAttribute(k_conv_mma, cudaFuncAttributeMaxDynamicSharedMemorySize, smem_conv);
    cudaFuncSetAttribute(k_path, cudaFuncAttributeMaxDynamicSharedMemorySize, smem_path);

    k_conv_mma<<<256, 256, smem_conv>>>(dz);
    k_path<<<N_PATHS / PPB, PT, smem_path>>>(dz, F0, alphas, rhos, nus, tau, L, Lam, out);
}